// round 10
// baseline (speedup 1.0000x reference)
#include <cuda_runtime.h>
#include <math.h>

#define C_CH   192
#define HW     56
#define NPIX   3136      // 56*56
#define NBATCH 64
#define NPLANE 12288     // 64*192
#define NCELL  602112    // 12288*49
#define N4TOT  9633792   // 64*192*3136/4
#define NBLK   444       // 148 SMs x 3 blocks (co-resident, guaranteed)
#define NUNIT1 6144      // pool units (2 planes each)
#define NCHUNK2 3072     // phase-2 chunks (4 planes = 3136 float4 each)

__constant__ float c_lowx[32] = {0,0,1,1,0,2,2,1,2,0,3,4,0,1,3,0,1,2,3,4,5,0,1,2,3,4,5,6,1,2,3,4};
__constant__ float c_lowy[32] = {0,1,0,1,2,0,1,2,2,3,0,0,4,3,1,5,4,3,2,1,0,6,5,4,3,2,1,0,6,5,4,3};

// Scratch (no allocations allowed -> __device__ globals)
__device__ float g_part[56 * 32];        // per-row gate partial sums (n=0 only)
__device__ float g_xp[NCELL];            // adaptive-avg-pooled x
__device__ float g_w1dT[192 * 192];      // transposed center tap of w1d: [c][o]
__device__ float g_scale[NPLANE];        // per-(n,c) scale
// persistent-kernel sync state (zero-init; reset by last block each run)
__device__ int g_u1;                     // phase-1 pool work counter
__device__ int g_sync1;                  // pool-done arrivals
__device__ int g_sync2;                  // scale-done count (target 64)
__device__ int g_done;                   // exit counter (last block resets all)

// ---------------------------------------------------------------------------
// Single persistent kernel: gate+pool -> grid barrier -> scale -> final.
// ---------------------------------------------------------------------------
__global__ __launch_bounds__(448, 3) void fused_kernel(
    const float* __restrict__ x, const float* __restrict__ wg1,
    const float* __restrict__ bng, const float* __restrict__ bnb,
    const float* __restrict__ bnm, const float* __restrict__ bnv,
    const float* __restrict__ wg2, const float* __restrict__ bg2,
    const float* __restrict__ beta, const float* __restrict__ w1d,
    const float* __restrict__ b1d,
    const float* __restrict__ bn1g, const float* __restrict__ bn1b,
    const float* __restrict__ bn1m, const float* __restrict__ bn1v,
    float* __restrict__ out)
{
    __shared__ float smem[192 * 32 + 56 * 33];   // 31.97 KB
    __shared__ int su;
    int t = threadIdx.x;
    int b = blockIdx.x;

    // ---- w1d center-tap transpose (blocks 360..443; before their pool work) ----
    if (b >= 360) {
        int i = (b - 360) * 448 + t;
        if (i < 192 * 192) {
            int o = i % 192, cc = i / 192;
            g_w1dT[i] = w1d[o * 576 + cc * 3 + 1];   // [c][o] layout
        }
    }

    // ---- gate path (blocks 0..55; batch element 0 only drives everything) ----
    if (b < 56) {
        float* sw    = smem;             // [192*32] sw[c*32+o] = wg1[o][c]
        float* sconv = smem + 192 * 32;  // [56*33] padded

        for (int i = t; i < 192 * 32; i += 448) {
            int c = i >> 5, o = i & 31;
            sw[i] = wg1[o * 192 + c];
        }
        for (int i = t; i < 56 * 33; i += 448) sconv[i] = 0.0f;
        __syncthreads();

        int px = t % 56;
        int q  = t / 56;                              // 0..7
        const float* xr = x + b * 56 + px;            // n=0, row=b
        float* dst = sconv + px * 33;
        int c0 = q * 24;

        for (int pass = 0; pass < 4; pass++) {
            int o0 = pass * 8;
            float acc[8];
#pragma unroll
            for (int u = 0; u < 8; u++) acc[u] = 0.0f;
#pragma unroll 4
            for (int c = c0; c < c0 + 24; c++) {
                float xv = __ldg(xr + c * NPIX);      // pass>0: L1 hit
                const float* w = sw + c * 32 + o0;
#pragma unroll
                for (int u = 0; u < 8; u++) acc[u] = fmaf(w[u], xv, acc[u]);
            }
#pragma unroll
            for (int u = 0; u < 8; u++) atomicAdd(dst + o0 + u, acc[u]);
        }
        __syncthreads();

        if (t < 32) {
            int o = t;
            float sc = bng[o] / sqrtf(bnv[o] + 1e-5f);
            float sh = bnb[o] - bnm[o] * sc;
            float s = 0.0f;
            for (int p = 0; p < 56; p++) {
                float v = fmaf(sconv[p * 33 + o], sc, sh);
                s += fmaxf(v, 0.0f);
            }
            g_part[b * 32 + o] = s;
        }
    }

    // ---- pool loop (all blocks, dynamic work: 2 planes per unit, MLP-4) ----
    for (;;) {
        __syncthreads();                      // smem reuse fence (also covers gate)
        if (t == 0) su = atomicAdd(&g_u1, 1);
        __syncthreads();
        int u = su;
        if (u >= NUNIT1) break;
        int nc0 = u * 2;
        if (t < 392) {
            const float4* p = (const float4*)(x + (size_t)nc0 * NPIX) + t * 2;
            float4 a0 = __ldg(p);
            float4 c0 = __ldg(p + 1);
            float4 a1 = __ldg(p + 784);
            float4 c1 = __ldg(p + 785);
            smem[t]       = (a0.x + a0.y + a0.z + a0.w) + (c0.x + c0.y + c0.z + c0.w);
            smem[392 + t] = (a1.x + a1.y + a1.z + a1.w) + (c1.x + c1.y + c1.z + c1.w);
        }
        __syncthreads();
        if (t < 98) {                         // 2 planes x 49 cells
            int pl = t / 49, cell = t % 49;
            int ci = cell / 7, cj = cell % 7;
            const float* sp = smem + pl * 392 + ci * 56 + cj;
            float s = 0.0f;
#pragma unroll
            for (int u8 = 0; u8 < 8; u8++) s += sp[u8 * 7];
            g_xp[(nc0 + pl) * 49 + cell] = s * (1.0f / 64.0f);
        }
    }

    // ---- grid barrier 1: all pool + gate + w1dT writes visible ----
    if (t == 0) {
        __threadfence();
        atomicAdd(&g_sync1, 1);
        while (*(volatile int*)&g_sync1 < NBLK) __nanosleep(64);
    }
    __syncthreads();

    // ---- scale phase (blocks 0..63, n = b); cross-block reads via __ldcg ----
    if (b < 64) {
        int n = b;
        float* sg     = smem;            // 32
        float* sxg    = smem + 32;       // 32
        float* sparam = smem + 64;       // 33
        float* sbasis = smem + 100;      // 1568
        float* syin   = smem + 1700;     // 192
        float* sy2    = smem + 1900;     // 384

        if (t < 32) {
            float s = 0.0f;
            for (int r = 0; r < 56; r++) s += __ldcg(&g_part[r * 32 + t]);
            sg[t] = s * (1.0f / 3136.0f);
        }
        __syncthreads();
        if (t < 32) {
            float a = bg2[t];
            for (int k = 0; k < 32; k++) a = fmaf(wg2[t * 32 + k], sg[k], a);
            sxg[t] = fmaxf(tanhf(a), 0.0f) + beta[0];
        }
        __syncthreads();
        if (t == 0) {
            float s = 0.0f;
            for (int i = 0; i < 32; i++) s += sxg[i];
            sparam[0] = 0.0f;
            float tot = 0.0f;
            for (int i = 1; i <= 31; i++) {
                float pv = rintf(sxg[i - 1] / s * 192.0f);  // == jnp.round
                sparam[i] = pv;
                tot += pv;
            }
            sparam[32] = 192.0f - tot;
        }
        const float PI = 3.14159265358979323846f;
        const float INV_SQRT7 = 0.37796447300922722721f;
        const float SQRT2 = 1.41421356237309504880f;
        for (int idx = t; idx < 32 * 49; idx += 448) {
            int bi = idx / 49, k = idx % 49;
            int tx = k / 7, ty = k % 7;
            float fx = c_lowx[bi], fy = c_lowy[bi];
            float bx = cosf(PI * fx * (tx + 0.5f) / 7.0f) * INV_SQRT7;
            if (fx != 0.0f) bx *= SQRT2;
            float by = cosf(PI * fy * (ty + 0.5f) / 7.0f) * INV_SQRT7;
            if (fy != 0.0f) by *= SQRT2;
            sbasis[idx] = bx * by;
        }
        __syncthreads();

        if (t < 192) {                    // yin[c]: last matching segment wins
            float cf = (float)t;
            int bid = -1;
            for (int i = 0; i < 32; i++)
                if (cf >= sparam[i] && cf < sparam[i + 1]) bid = i;
            float yv = 0.0f;
            if (bid >= 0) {
                const float* xpp = g_xp + (n * 192 + t) * 49;
                const float* bb = sbasis + bid * 49;
#pragma unroll
                for (int k = 0; k < 49; k++) yv = fmaf(__ldcg(xpp + k), bb[k], yv);
            }
            syin[t] = yv;
        }
        __syncthreads();
        if (t < 384) {                    // split GEMV (2 halves of 96 channels)
            int half = t / 192, o = t % 192;
            float a = 0.0f;
            int cb = half * 96;
            for (int c = cb; c < cb + 96; c++)
                a = fmaf(__ldcg(&g_w1dT[c * 192 + o]), syin[c], a);
            sy2[t] = a;
        }
        __syncthreads();
        if (t < 192) {
            float a = sy2[t] + sy2[192 + t] + b1d[t];
            float sc = bn1g[t] / sqrtf(bn1v[t] + 1e-5f);
            a = (a - bn1m[t]) * sc + bn1b[t];
            g_scale[n * 192 + t] = fmaxf(a, 0.0f);
        }
        __threadfence();
        __syncthreads();
        if (t == 0) atomicAdd(&g_sync2, 1);
    }

    // ---- grid barrier 2: scales ready ----
    if (t == 0) {
        while (*(volatile int*)&g_sync2 < 64) __nanosleep(64);
    }
    __syncthreads();

    // ---- phase 2: out = x*(1+scale), reverse order, streaming stores ----
    {
        const float4* x4 = (const float4*)x;
        float4* o4 = (float4*)out;
        for (int i = b; i < NCHUNK2; i += NBLK) {
            int chunk = NCHUNK2 - 1 - i;            // high addresses first (L2 tail)
            size_t base = (size_t)chunk * 3136;
            int nc0 = chunk * 4;
#pragma unroll
            for (int k = 0; k < 7; k++) {
                int idx = k * 448 + t;
                int pl = idx / 784;
                float s = 1.0f + __ldcg(&g_scale[nc0 + pl]);
                float4 v = __ldg(x4 + base + idx);
                v.x *= s; v.y *= s; v.z *= s; v.w *= s;
                __stcs(o4 + base + idx, v);
            }
        }
    }

    // ---- exit: last block resets sync state for the next (graph) replay ----
    if (t == 0) {
        int v = atomicAdd(&g_done, 1);
        if (v == NBLK - 1) {
            g_u1 = 0; g_sync1 = 0; g_sync2 = 0; g_done = 0;
            __threadfence();
        }
    }
}

// ---------------------------------------------------------------------------
// Inputs (metadata order): x, wg1, bn2_g, bn2_b, bn2_m, bn2_v,
//                          wg2, bg2, beta, w1d, b1d, bn1_g, bn1_b, bn1_m, bn1_v
// ---------------------------------------------------------------------------
extern "C" void kernel_launch(void* const* d_in, const int* in_sizes, int n_in,
                              void* d_out, int out_size)
{
    const float* x     = (const float*)d_in[0];
    const float* wg1   = (const float*)d_in[1];
    const float* bn2g  = (const float*)d_in[2];
    const float* bn2b  = (const float*)d_in[3];
    const float* bn2m  = (const float*)d_in[4];
    const float* bn2v  = (const float*)d_in[5];
    const float* wg2   = (const float*)d_in[6];
    const float* bg2   = (const float*)d_in[7];
    const float* beta  = (const float*)d_in[8];
    const float* w1d   = (const float*)d_in[9];
    const float* b1d   = (const float*)d_in[10];
    const float* bn1g  = (const float*)d_in[11];
    const float* bn1b  = (const float*)d_in[12];
    const float* bn1m  = (const float*)d_in[13];
    const float* bn1v  = (const float*)d_in[14];
    float* out = (float*)d_out;

    fused_kernel<<<NBLK, 448>>>(x, wg1, bn2g, bn2b, bn2m, bn2v,
                                wg2, bg2, beta, w1d, b1d,
                                bn1g, bn1b, bn1m, bn1v, out);
}

// round 11
// speedup vs baseline: 1.0353x; 1.0353x over previous
#include <cuda_runtime.h>
#include <math.h>

#define C_CH   192
#define HW     56
#define NPIX   3136      // 56*56
#define NBATCH 64
#define NPLANE 12288     // 64*192
#define NCELL  602112    // 12288*49
#define N4TOT  9633792   // 64*192*3136/4
#define PPB    2
#define POOLBLK (NPLANE / PPB)   // 6144
#define FCHUNK 1024              // float4 per final block
#define FBLK   (N4TOT / FCHUNK)  // 9408

__constant__ float c_lowx[32] = {0,0,1,1,0,2,2,1,2,0,3,4,0,1,3,0,1,2,3,4,5,0,1,2,3,4,5,6,1,2,3,4};
__constant__ float c_lowy[32] = {0,1,0,1,2,0,1,2,2,3,0,0,4,3,1,5,4,3,2,1,0,6,5,4,3,2,1,0,6,5,4,3};

// Scratch (no allocations allowed -> __device__ globals)
__device__ float g_part[56 * 32];        // per-row gate partial sums (n=0 only)
__device__ float g_xp[NCELL];            // adaptive-avg-pooled x
__device__ float g_w1dT[192 * 192];      // transposed center tap of w1d: [c][o]
__device__ float g_yin[NBATCH * 192];    // DCT-pooled features
__device__ float g_scale[NPLANE];        // final per-(n,c) scale

// ---------------------------------------------------------------------------
// Fused gate+pool kernel (R8 shape: DRAM 71%, 28.3us).
// ---------------------------------------------------------------------------
__global__ __launch_bounds__(448, 3) void poolgate_kernel(
    const float* __restrict__ x, const float* __restrict__ wg1,
    const float* __restrict__ bng, const float* __restrict__ bnb,
    const float* __restrict__ bnm, const float* __restrict__ bnv,
    const float* __restrict__ w1d)
{
    __shared__ float smem[192 * 32 + 56 * 33];
    int t = threadIdx.x;
    int b = blockIdx.x;

    if (b < 56) {
        // ---------------- gate path (batch element 0 only) ----------------
        float* sw    = smem;             // [192*32] sw[c*32+o] = wg1[o][c]
        float* sconv = smem + 192 * 32;  // [56*33] padded

        for (int i = t; i < 192 * 32; i += 448) {
            int c = i >> 5, o = i & 31;
            sw[i] = wg1[o * 192 + c];
        }
        for (int i = t; i < 56 * 33; i += 448) sconv[i] = 0.0f;
        __syncthreads();

        int px = t % 56;
        int q  = t / 56;
        const float* xr = x + b * 56 + px;
        float* dst = sconv + px * 33;
        int c0 = q * 24;

        for (int pass = 0; pass < 4; pass++) {
            int o0 = pass * 8;
            float acc[8];
#pragma unroll
            for (int u = 0; u < 8; u++) acc[u] = 0.0f;
#pragma unroll 4
            for (int c = c0; c < c0 + 24; c++) {
                float xv = __ldg(xr + c * NPIX);
                const float* w = sw + c * 32 + o0;
#pragma unroll
                for (int u = 0; u < 8; u++) acc[u] = fmaf(w[u], xv, acc[u]);
            }
#pragma unroll
            for (int u = 0; u < 8; u++) atomicAdd(dst + o0 + u, acc[u]);
        }
        __syncthreads();

        if (t < 32) {
            int o = t;
            float sc = bng[o] / sqrtf(bnv[o] + 1e-5f);
            float sh = bnb[o] - bnm[o] * sc;
            float s = 0.0f;
            for (int p = 0; p < 56; p++) {
                float v = fmaf(sconv[p * 33 + o], sc, sh);
                s += fmaxf(v, 0.0f);
            }
            g_part[b * 32 + o] = s;
        }
    } else {
        // ---------------- pool path (2 planes, MLP-4) ----------------
        int pb  = b - 56;
        int nc0 = pb * PPB;

        if (pb < 83) {                   // w1d center-tap transpose
            int i = pb * 448 + t;
            if (i < 192 * 192) {
                int o = i % 192, cc = i / 192;
                g_w1dT[i] = w1d[o * 576 + cc * 3 + 1];   // [c][o] layout
            }
        }

        if (t < 392) {
            const float4* p = (const float4*)(x + (size_t)nc0 * NPIX) + t * 2;
            float4 a0 = __ldg(p);
            float4 c0 = __ldg(p + 1);
            float4 a1 = __ldg(p + 784);
            float4 c1 = __ldg(p + 785);
            smem[t]       = (a0.x + a0.y + a0.z + a0.w) + (c0.x + c0.y + c0.z + c0.w);
            smem[392 + t] = (a1.x + a1.y + a1.z + a1.w) + (c1.x + c1.y + c1.z + c1.w);
        }
        __syncthreads();
        if (t < 98) {
            int pl = t / 49, cell = t % 49;
            int ci = cell / 7, cj = cell % 7;
            const float* sp = smem + pl * 392 + ci * 56 + cj;
            float s = 0.0f;
#pragma unroll
            for (int u = 0; u < 8; u++) s += sp[u * 7];
            g_xp[(nc0 + pl) * 49 + cell] = s * (1.0f / 64.0f);
        }
    }
}

// ---------------------------------------------------------------------------
// S1: yin[n,c] = <xp[n,c,:,:], filt[c]>   (param+basis recomputed per block)
// ---------------------------------------------------------------------------
__global__ __launch_bounds__(192) void yin_kernel(
    const float* __restrict__ wg2, const float* __restrict__ bg2,
    const float* __restrict__ beta)
{
    __shared__ float sg[32];
    __shared__ float sxg[32];
    __shared__ float sparam[33];
    __shared__ float sbasis[32 * 49];

    int n = blockIdx.x, t = threadIdx.x;

    if (t < 32) {
        float s = 0.0f;
        for (int b = 0; b < 56; b++) s += g_part[b * 32 + t];
        sg[t] = s * (1.0f / 3136.0f);
    }
    __syncthreads();
    if (t < 32) {
        float a = bg2[t];
        for (int k = 0; k < 32; k++) a = fmaf(wg2[t * 32 + k], sg[k], a);
        sxg[t] = fmaxf(tanhf(a), 0.0f) + beta[0];
    }
    __syncthreads();
    if (t == 0) {
        float s = 0.0f;
        for (int i = 0; i < 32; i++) s += sxg[i];
        sparam[0] = 0.0f;
        float tot = 0.0f;
        for (int i = 1; i <= 31; i++) {
            float pv = rintf(sxg[i - 1] / s * 192.0f);  // rintf == jnp.round
            sparam[i] = pv;
            tot += pv;
        }
        sparam[32] = 192.0f - tot;
    }
    const float PI = 3.14159265358979323846f;
    const float INV_SQRT7 = 0.37796447300922722721f;
    const float SQRT2 = 1.41421356237309504880f;
    for (int idx = t; idx < 32 * 49; idx += 192) {
        int bi = idx / 49, k = idx % 49;
        int tx = k / 7, ty = k % 7;
        float fx = c_lowx[bi], fy = c_lowy[bi];
        float bx = cosf(PI * fx * (tx + 0.5f) / 7.0f) * INV_SQRT7;
        if (fx != 0.0f) bx *= SQRT2;
        float by = cosf(PI * fy * (ty + 0.5f) / 7.0f) * INV_SQRT7;
        if (fy != 0.0f) by *= SQRT2;
        sbasis[idx] = bx * by;
    }
    __syncthreads();

    // last segment i with param[i] <= c < param[i+1] wins (matches overwrite)
    float cf = (float)t;
    int bid = -1;
    for (int i = 0; i < 32; i++)
        if (cf >= sparam[i] && cf < sparam[i + 1]) bid = i;
    float yv = 0.0f;
    if (bid >= 0) {
        const float* xpp = g_xp + (n * 192 + t) * 49;
        const float* bb = sbasis + bid * 49;
#pragma unroll
        for (int k = 0; k < 49; k++) yv = fmaf(xpp[k], bb[k], yv);
    }
    g_yin[n * 192 + t] = yv;
}

// ---------------------------------------------------------------------------
// S2: y = yin @ W^T (+bias, BN, ReLU) -> g_scale.  Fully smem-tiled:
// 48 blocks x 256 thr; block = (o-group of 8) x (n-group of 32).
// Loads 32 yin rows (24KB) + 8 W columns (6KB) into smem; each thread does
// one dot-192 from smem (29-cyc LDS, deep pipelining; no L2 latency chain).
// ---------------------------------------------------------------------------
__global__ __launch_bounds__(256) void gemm_kernel(
    const float* __restrict__ b1d,
    const float* __restrict__ bn1g, const float* __restrict__ bn1b,
    const float* __restrict__ bn1m, const float* __restrict__ bn1v)
{
    __shared__ float syin[32 * 192];   // 24 KB
    __shared__ float sw[192 * 8];      // 6 KB

    int t = threadIdx.x;
    int og = blockIdx.x % 24;          // 8 outputs per group
    int ng = blockIdx.x / 24;          // 32 batch rows per group

    const float* yb = g_yin + ng * 32 * 192;
    for (int i = t; i < 32 * 192; i += 256) syin[i] = yb[i];
    for (int i = t; i < 192 * 8; i += 256) {
        int c = i >> 3, oo = i & 7;
        sw[i] = g_w1dT[c * 192 + og * 8 + oo];
    }
    __syncthreads();

    int nl = t >> 3;                   // 0..31
    int oo = t & 7;                    // 0..7
    int o  = og * 8 + oo;
    const float* yr = syin + nl * 192;
    float a = 0.0f;
#pragma unroll 8
    for (int c = 0; c < 192; c++) a = fmaf(yr[c], sw[c * 8 + oo], a);
    a += b1d[o];
    float sc = bn1g[o] / sqrtf(bn1v[o] + 1e-5f);
    a = (a - bn1m[o]) * sc + bn1b[o];
    g_scale[(ng * 32 + nl) * 192 + o] = fmaxf(a, 0.0f);
}

// ---------------------------------------------------------------------------
// Final: out = x*(1+scale).  4 independent float4 per thread (MLP-4),
// reverse block order (L2-tail reuse), streaming stores.
// ---------------------------------------------------------------------------
__global__ __launch_bounds__(256) void final_kernel(
    const float* __restrict__ x, float* __restrict__ out)
{
    const float4* x4 = (const float4*)x;
    float4* o4 = (float4*)out;
    int t = threadIdx.x;
    size_t base = (size_t)(FBLK - 1 - blockIdx.x) * FCHUNK;

    float4 v0 = __ldg(x4 + base + t);
    float4 v1 = __ldg(x4 + base + 256 + t);
    float4 v2 = __ldg(x4 + base + 512 + t);
    float4 v3 = __ldg(x4 + base + 768 + t);

    int i0 = (int)(base + t);
    float s0 = 1.0f + __ldg(&g_scale[i0 / 784]);
    float s1 = 1.0f + __ldg(&g_scale[(i0 + 256) / 784]);
    float s2 = 1.0f + __ldg(&g_scale[(i0 + 512) / 784]);
    float s3 = 1.0f + __ldg(&g_scale[(i0 + 768) / 784]);

    v0.x *= s0; v0.y *= s0; v0.z *= s0; v0.w *= s0;
    v1.x *= s1; v1.y *= s1; v1.z *= s1; v1.w *= s1;
    v2.x *= s2; v2.y *= s2; v2.z *= s2; v2.w *= s2;
    v3.x *= s3; v3.y *= s3; v3.z *= s3; v3.w *= s3;

    __stcs(o4 + base + t, v0);
    __stcs(o4 + base + 256 + t, v1);
    __stcs(o4 + base + 512 + t, v2);
    __stcs(o4 + base + 768 + t, v3);
}

// ---------------------------------------------------------------------------
// Inputs (metadata order): x, wg1, bn2_g, bn2_b, bn2_m, bn2_v,
//                          wg2, bg2, beta, w1d, b1d, bn1_g, bn1_b, bn1_m, bn1_v
// ---------------------------------------------------------------------------
extern "C" void kernel_launch(void* const* d_in, const int* in_sizes, int n_in,
                              void* d_out, int out_size)
{
    const float* x     = (const float*)d_in[0];
    const float* wg1   = (const float*)d_in[1];
    const float* bn2g  = (const float*)d_in[2];
    const float* bn2b  = (const float*)d_in[3];
    const float* bn2m  = (const float*)d_in[4];
    const float* bn2v  = (const float*)d_in[5];
    const float* wg2   = (const float*)d_in[6];
    const float* bg2   = (const float*)d_in[7];
    const float* beta  = (const float*)d_in[8];
    const float* w1d   = (const float*)d_in[9];
    const float* b1d   = (const float*)d_in[10];
    const float* bn1g  = (const float*)d_in[11];
    const float* bn1b  = (const float*)d_in[12];
    const float* bn1m  = (const float*)d_in[13];
    const float* bn1v  = (const float*)d_in[14];
    float* out = (float*)d_out;

    poolgate_kernel<<<56 + POOLBLK, 448>>>(x, wg1, bn2g, bn2b, bn2m, bn2v, w1d);
    yin_kernel<<<64, 192>>>(wg2, bg2, beta);
    gemm_kernel<<<48, 256>>>(b1d, bn1g, bn1b, bn1m, bn1v);
    final_kernel<<<FBLK, 256>>>(x, out);
}